// round 1
// baseline (speedup 1.0000x reference)
#include <cuda_runtime.h>
#include <cstdint>
#include <cstdio>

// ---------------------------------------------------------------------------
// GNNDecoder: h = PReLU(x) @ Wenc^T ; h[mask]=0 ; aggr = segsum(h[src]+emb) ;
//             out = relu(aggr@W1^T+b1) @ W2^T + b2
// ---------------------------------------------------------------------------

#define MAXN 50176   // N=50000 padded

// Scratch (device globals; no allocation allowed)
__device__ float g_h[MAXN * 128];
__device__ float g_aggr[MAXN * 128];
__device__ float g_t[MAXN * 256];
__device__ float g_embc[18 * 128];   // emb1[t] + emb2[d], combo idx t*3+d. idx 12 = self-loop [4,0]

// ---------------------------------------------------------------------------
// Setup: precompute edge-embedding combos
// ---------------------------------------------------------------------------
__global__ void setup_emb_kernel(const float* __restrict__ emb1,
                                 const float* __restrict__ emb2) {
    int i = threadIdx.x;  // 128 threads
    #pragma unroll
    for (int t = 0; t < 6; t++)
        #pragma unroll
        for (int d = 0; d < 3; d++)
            g_embc[(t * 3 + d) * 128 + i] = emb1[t * 128 + i] + emb2[d * 128 + i];
}

// ---------------------------------------------------------------------------
// Generic fp32 GEMM: C[M, Ntot] = f_out( f_in(A)[M,K] @ B[Ntot,K]^T + bias )
// B is row-major [out_features, K] (PyTorch/JAX weight layout).
// Tile: BM=64, BN=128, full K resident in smem. 256 threads, 4x8 micro-tile.
// DUAL: additionally writes C2 = C + addvec (broadcast over rows).
// ---------------------------------------------------------------------------
template <int K, bool PRELU, bool RELU_OUT, bool BIAS, bool DUAL>
__global__ void __launch_bounds__(256)
gemm_kernel(const float* __restrict__ A, const float* __restrict__ B,
            const float* __restrict__ bias, const float* __restrict__ prelu_pa,
            float* __restrict__ C, float* __restrict__ C2,
            const float* __restrict__ addvec, int M, int Ntot) {
    constexpr int AP = 68;    // padded row length for AsT [K][64+4]
    constexpr int BP = 136;   // padded row length for BsT [K][128+8]
    extern __shared__ float smem[];
    float* AsT = smem;            // [K][AP]  (transposed A tile)
    float* BsT = smem + K * AP;   // [K][BP]  (transposed B tile)

    const int tid = threadIdx.x;
    const int rowbase = blockIdx.x * 64;
    const int colbase = blockIdx.y * 128;

    float pa = 0.0f;
    if (PRELU) pa = *prelu_pa;

    // ---- load + transpose A tile (row-fastest: conflict-free STS) ----
    #pragma unroll
    for (int i = tid; i < 64 * K / 4; i += 256) {
        int row = i & 63;
        int kq  = i >> 6;
        int gr  = rowbase + row;
        float4 v = make_float4(0.f, 0.f, 0.f, 0.f);
        if (gr < M)
            v = *reinterpret_cast<const float4*>(A + (size_t)gr * K + kq * 4);
        if (PRELU) {
            v.x = v.x > 0.f ? v.x : pa * v.x;
            v.y = v.y > 0.f ? v.y : pa * v.y;
            v.z = v.z > 0.f ? v.z : pa * v.z;
            v.w = v.w > 0.f ? v.w : pa * v.w;
        }
        AsT[(4 * kq + 0) * AP + row] = v.x;
        AsT[(4 * kq + 1) * AP + row] = v.y;
        AsT[(4 * kq + 2) * AP + row] = v.z;
        AsT[(4 * kq + 3) * AP + row] = v.w;
    }

    // ---- load + transpose B tile ----
    #pragma unroll
    for (int i = tid; i < 128 * K / 4; i += 256) {
        int row = i & 127;
        int kq  = i >> 7;
        float4 v = *reinterpret_cast<const float4*>(B + (size_t)(colbase + row) * K + kq * 4);
        BsT[(4 * kq + 0) * BP + row] = v.x;
        BsT[(4 * kq + 1) * BP + row] = v.y;
        BsT[(4 * kq + 2) * BP + row] = v.z;
        BsT[(4 * kq + 3) * BP + row] = v.w;
    }

    __syncthreads();

    const int tx = tid & 15;   // 16 col-groups of 8 cols
    const int ty = tid >> 4;   // 16 row-groups of 4 rows

    float acc[4][8];
    #pragma unroll
    for (int r = 0; r < 4; r++)
        #pragma unroll
        for (int c = 0; c < 8; c++) acc[r][c] = 0.f;

    #pragma unroll 8
    for (int k = 0; k < K; k++) {
        float4 a  = *reinterpret_cast<const float4*>(&AsT[k * AP + 4 * ty]);
        float4 b0 = *reinterpret_cast<const float4*>(&BsT[k * BP + 8 * tx]);
        float4 b1 = *reinterpret_cast<const float4*>(&BsT[k * BP + 8 * tx + 4]);
        float av[4] = {a.x, a.y, a.z, a.w};
        float bv[8] = {b0.x, b0.y, b0.z, b0.w, b1.x, b1.y, b1.z, b1.w};
        #pragma unroll
        for (int r = 0; r < 4; r++)
            #pragma unroll
            for (int c = 0; c < 8; c++)
                acc[r][c] += av[r] * bv[c];
    }

    // ---- epilogue ----
    const int gc = colbase + 8 * tx;
    float bvec[8];
    #pragma unroll
    for (int c = 0; c < 8; c++) bvec[c] = 0.f;
    if (BIAS) {
        float4 t0 = *reinterpret_cast<const float4*>(bias + gc);
        float4 t1 = *reinterpret_cast<const float4*>(bias + gc + 4);
        bvec[0] = t0.x; bvec[1] = t0.y; bvec[2] = t0.z; bvec[3] = t0.w;
        bvec[4] = t1.x; bvec[5] = t1.y; bvec[6] = t1.z; bvec[7] = t1.w;
    }
    float avec[8];
    if (DUAL) {
        float4 t0 = *reinterpret_cast<const float4*>(addvec + gc);
        float4 t1 = *reinterpret_cast<const float4*>(addvec + gc + 4);
        avec[0] = t0.x; avec[1] = t0.y; avec[2] = t0.z; avec[3] = t0.w;
        avec[4] = t1.x; avec[5] = t1.y; avec[6] = t1.z; avec[7] = t1.w;
    }

    #pragma unroll
    for (int r = 0; r < 4; r++) {
        int gr = rowbase + 4 * ty + r;
        if (gr >= M) continue;
        float o[8];
        #pragma unroll
        for (int c = 0; c < 8; c++) {
            float v = acc[r][c];
            if (BIAS) v += bvec[c];
            if (RELU_OUT) v = v > 0.f ? v : 0.f;
            o[c] = v;
        }
        float* cp = C + (size_t)gr * Ntot + gc;
        *reinterpret_cast<float4*>(cp)     = make_float4(o[0], o[1], o[2], o[3]);
        *reinterpret_cast<float4*>(cp + 4) = make_float4(o[4], o[5], o[6], o[7]);
        if (DUAL) {
            float* cp2 = C2 + (size_t)gr * Ntot + gc;
            *reinterpret_cast<float4*>(cp2)     = make_float4(o[0] + avec[0], o[1] + avec[1],
                                                              o[2] + avec[2], o[3] + avec[3]);
            *reinterpret_cast<float4*>(cp2 + 4) = make_float4(o[4] + avec[4], o[5] + avec[5],
                                                              o[6] + avec[6], o[7] + avec[7]);
        }
    }
}

// ---------------------------------------------------------------------------
// Mask fix: h[m] = 0 ; aggr[m] = selfc (= embc[12])
// One warp per masked index; idempotent under duplicate indices.
// ---------------------------------------------------------------------------
__global__ void mask_kernel(const int* __restrict__ mask, int Mm) {
    int g = blockIdx.x * blockDim.x + threadIdx.x;
    int i = g >> 5;
    int lane = g & 31;
    if (i >= Mm) return;
    int row = __ldg(mask + i);
    *reinterpret_cast<float4*>(g_h + (size_t)row * 128 + lane * 4) =
        make_float4(0.f, 0.f, 0.f, 0.f);
    *reinterpret_cast<float4*>(g_aggr + (size_t)row * 128 + lane * 4) =
        *reinterpret_cast<const float4*>(g_embc + 12 * 128 + lane * 4);
}

// ---------------------------------------------------------------------------
// Edge scatter: one warp per edge. aggr[dst] += h[src] + embc[a0*3+a1]
// h/aggr are L2-resident (25.6 MB each). Vector fp32 reduction atomics.
// ---------------------------------------------------------------------------
__global__ void scatter_kernel(const int* __restrict__ ei,
                               const int* __restrict__ ea, int E) {
    int g = blockIdx.x * blockDim.x + threadIdx.x;
    int e = g >> 5;
    int lane = g & 31;
    if (e >= E) return;
    int src = __ldg(ei + e);
    int dst = __ldg(ei + E + e);
    int a0  = __ldg(ea + 2 * e);
    int a1  = __ldg(ea + 2 * e + 1);

    float4 hv = *reinterpret_cast<const float4*>(g_h + (size_t)src * 128 + lane * 4);
    float4 ev = *reinterpret_cast<const float4*>(g_embc + (a0 * 3 + a1) * 128 + lane * 4);
    float4 m = make_float4(hv.x + ev.x, hv.y + ev.y, hv.z + ev.z, hv.w + ev.w);

    float* p = g_aggr + (size_t)dst * 128 + lane * 4;
    asm volatile("red.global.add.v4.f32 [%0], {%1, %2, %3, %4};"
                 :: "l"(p), "f"(m.x), "f"(m.y), "f"(m.z), "f"(m.w)
                 : "memory");
}

// ---------------------------------------------------------------------------
// Host launch
// ---------------------------------------------------------------------------
extern "C" void kernel_launch(void* const* d_in, const int* in_sizes, int n_in,
                              void* d_out, int out_size) {
    const float* x    = (const float*)d_in[0];
    const int*   ei   = (const int*)d_in[1];
    const int*   ea   = (const int*)d_in[2];
    const int*   mask = (const int*)d_in[3];
    const float* pa   = (const float*)d_in[4];
    const float* Wenc = (const float*)d_in[5];
    const float* W1   = (const float*)d_in[6];
    const float* b1   = (const float*)d_in[7];
    const float* W2   = (const float*)d_in[8];
    const float* b2   = (const float*)d_in[9];
    const float* emb1 = (const float*)d_in[10];
    const float* emb2 = (const float*)d_in[11];

    int N  = in_sizes[0] / 128;
    int E  = in_sizes[1] / 2;
    int Mm = in_sizes[3];
    float* out = (float*)d_out;

    float *h, *aggr, *t, *embc;
    cudaGetSymbolAddress((void**)&h,    g_h);
    cudaGetSymbolAddress((void**)&aggr, g_aggr);
    cudaGetSymbolAddress((void**)&t,    g_t);
    cudaGetSymbolAddress((void**)&embc, g_embc);

    constexpr int SMEM128 = 128 * (68 + 136) * 4;  // 104448 B
    constexpr int SMEM256 = 256 * (68 + 136) * 4;  // 208896 B
    cudaFuncSetAttribute(gemm_kernel<128, true,  false, false, true>,
                         cudaFuncAttributeMaxDynamicSharedMemorySize, SMEM128);
    cudaFuncSetAttribute(gemm_kernel<128, false, true,  true,  false>,
                         cudaFuncAttributeMaxDynamicSharedMemorySize, SMEM128);
    cudaFuncSetAttribute(gemm_kernel<256, false, false, true,  false>,
                         cudaFuncAttributeMaxDynamicSharedMemorySize, SMEM256);

    // 1) edge-embedding combos
    setup_emb_kernel<<<1, 128>>>(emb1, emb2);

    // 2) G1: h = PReLU(x) @ Wenc^T ; aggr = h + selfc (self-loop init)
    dim3 g1((N + 63) / 64, 1);
    gemm_kernel<128, true, false, false, true><<<g1, 256, SMEM128>>>(
        x, Wenc, nullptr, pa, h, aggr, embc + 12 * 128, N, 128);

    // 3) mask: h[m]=0, aggr[m]=selfc
    mask_kernel<<<(Mm * 32 + 255) / 256, 256>>>(mask, Mm);

    // 4) edge scatter (atomic accumulate into aggr)
    long long nthr = (long long)E * 32;
    scatter_kernel<<<(unsigned)((nthr + 255) / 256), 256>>>(ei, ea, E);

    // 5) G2: t = relu(aggr @ W1^T + b1)   [N,128] x [256,128]^T
    dim3 g2((N + 63) / 64, 2);
    gemm_kernel<128, false, true, true, false><<<g2, 256, SMEM128>>>(
        aggr, W1, b1, nullptr, t, nullptr, nullptr, N, 256);

    // 6) G3: out = t @ W2^T + b2          [N,256] x [128,256]^T
    dim3 g3((N + 63) / 64, 1);
    gemm_kernel<256, false, false, true, false><<<g3, 256, SMEM256>>>(
        t, W2, b2, nullptr, out, nullptr, nullptr, N, 128);
}